// round 1
// baseline (speedup 1.0000x reference)
#include <cuda_runtime.h>
#include <cstdint>

#define BATCH 4096
#define DIM   768
#define NEXP  16
#define KD    1536
#define TOPE  2
#define KSEL  50
#define NPAIR (BATCH*TOPE)

// ---------------- device scratch (no allocations allowed) ----------------
__device__ float g_F[NPAIR * KD];   // masked relu activations, 50.3 MB
__device__ float g_w[NPAIR];        // gate weight per (token,slot)
__device__ int   g_route[NPAIR];    // expert id per (token,slot)
__device__ int   g_cnt[NEXP];       // tokens routed to each expert
__device__ int   g_list[NEXP * BATCH]; // pair ids per expert

// ---------------- init ----------------
__global__ void k_init() {
    if (threadIdx.x < NEXP) g_cnt[threadIdx.x] = 0;
}

// ---------------- gate + route: one warp per token ----------------
__global__ void __launch_bounds__(128) k_gate(const float* __restrict__ x,
                                              const float* __restrict__ Wg,
                                              const float* __restrict__ bg,
                                              const float* __restrict__ b_gate) {
    int b = blockIdx.x * 4 + (threadIdx.x >> 5);
    int lane = threadIdx.x & 31;
    const float* xr = x + (size_t)b * DIM;

    float pe[NEXP];
#pragma unroll
    for (int e = 0; e < NEXP; e++) pe[e] = 0.f;

    for (int d = lane; d < DIM; d += 32) {
        float xv = xr[d] - b_gate[d];
#pragma unroll
        for (int e = 0; e < NEXP; e++) pe[e] += xv * Wg[e * DIM + d];
    }
#pragma unroll
    for (int e = 0; e < NEXP; e++) {
#pragma unroll
        for (int o = 16; o > 0; o >>= 1) pe[e] += __shfl_xor_sync(0xffffffffu, pe[e], o);
        pe[e] += bg[e];
    }
    // softmax over 16 logits (every lane redundantly)
    float m = pe[0];
#pragma unroll
    for (int e = 1; e < NEXP; e++) m = fmaxf(m, pe[e]);
    float s = 0.f;
#pragma unroll
    for (int e = 0; e < NEXP; e++) { pe[e] = expf(pe[e] - m); s += pe[e]; }
    float inv = 1.f / s;
    // top-2 of probabilities (ties -> lower index, matching jax top_k)
    float v1 = -1.f, v2 = -1.f; int i1 = 0, i2 = 0;
#pragma unroll
    for (int e = 0; e < NEXP; e++) {
        float p = pe[e] * inv;
        if (p > v1)      { v2 = v1; i2 = i1; v1 = p; i1 = e; }
        else if (p > v2) { v2 = p;  i2 = e; }
    }
    // second softmax over the two kept probabilities
    float e1 = expf(v1), e2 = expf(v2);
    float w0 = e1 / (e1 + e2), w1 = e2 / (e1 + e2);

    if (lane == 0) {
        int p0 = b * 2, p1 = b * 2 + 1;
        g_route[p0] = i1; g_route[p1] = i2;
        g_w[p0] = w0;     g_w[p1] = w1;
        int q0 = atomicAdd(&g_cnt[i1], 1); g_list[i1 * BATCH + q0] = p0;
        int q1 = atomicAdd(&g_cnt[i2], 1); g_list[i2 * BATCH + q1] = p1;
    }
}

// ---------------- grouped encode GEMM: f = relu((x-b_dec)@We^T + benc)*w ----------------
// tile: 64 rows (token,slot pairs) x 64 dict cols, K-chunks of 16
#define TM 64
#define TN 64
#define TK 16

__global__ void __launch_bounds__(256) k_encode(const float* __restrict__ x,
                                                const float* __restrict__ b_dec,
                                                const float* __restrict__ Wenc,
                                                const float* __restrict__ benc) {
    int e  = blockIdx.y >> 6;
    int mt = blockIdx.y & 63;
    int cnt = g_cnt[e];
    int m0 = mt * TM;
    if (m0 >= cnt) return;
    int n0 = blockIdx.x * TN;

    __shared__ float Xs[TK][TM + 4];   // 68-float rows: 16B-aligned, conflict-reduced
    __shared__ float Ws[TK][TN + 4];
    __shared__ int   s_pair[TM];

    int tid = threadIdx.x;
    if (tid < TM) {
        int m = m0 + tid;
        s_pair[tid] = (m < cnt) ? g_list[e * BATCH + m] : -1;
    }
    __syncthreads();

    int tx = tid & 15, ty = tid >> 4;
    float acc[4][4];
#pragma unroll
    for (int i = 0; i < 4; i++)
#pragma unroll
        for (int j = 0; j < 4; j++) acc[i][j] = 0.f;

    const float* We = Wenc + (size_t)e * KD * DIM;

    // loader mapping: each thread loads one float4 per tile
    int lr = tid >> 2;          // 0..63 row within tile
    int lc = (tid & 3) * 4;     // 0,4,8,12 col offset
    int pairL = s_pair[lr];
    int tokenL = (pairL >= 0 ? pairL : 0) >> 1;
    const float* xrow = x + (size_t)tokenL * DIM;
    const float* wrow = We + (size_t)(n0 + lr) * DIM;

    for (int k0 = 0; k0 < DIM; k0 += TK) {
        float4 xa = *(const float4*)(xrow + k0 + lc);
        float4 bd = *(const float4*)(b_dec + k0 + lc);
        xa.x -= bd.x; xa.y -= bd.y; xa.z -= bd.z; xa.w -= bd.w;
        Xs[lc + 0][lr] = xa.x; Xs[lc + 1][lr] = xa.y;
        Xs[lc + 2][lr] = xa.z; Xs[lc + 3][lr] = xa.w;
        float4 wa = *(const float4*)(wrow + k0 + lc);
        Ws[lc + 0][lr] = wa.x; Ws[lc + 1][lr] = wa.y;
        Ws[lc + 2][lr] = wa.z; Ws[lc + 3][lr] = wa.w;
        __syncthreads();
#pragma unroll
        for (int kk = 0; kk < TK; kk++) {
            float4 a = *(const float4*)&Xs[kk][ty * 4];
            float4 v = *(const float4*)&Ws[kk][tx * 4];
            acc[0][0] += a.x * v.x; acc[0][1] += a.x * v.y; acc[0][2] += a.x * v.z; acc[0][3] += a.x * v.w;
            acc[1][0] += a.y * v.x; acc[1][1] += a.y * v.y; acc[1][2] += a.y * v.z; acc[1][3] += a.y * v.w;
            acc[2][0] += a.z * v.x; acc[2][1] += a.z * v.y; acc[2][2] += a.z * v.z; acc[2][3] += a.z * v.w;
            acc[3][0] += a.w * v.x; acc[3][1] += a.w * v.y; acc[3][2] += a.w * v.z; acc[3][3] += a.w * v.w;
        }
        __syncthreads();
    }

    const float* be = benc + (size_t)e * KD + n0 + tx * 4;
#pragma unroll
    for (int im = 0; im < 4; im++) {
        int m = ty * 4 + im;
        int pair = s_pair[m];
        if (pair < 0) continue;
        float w = g_w[pair];
        float4 r;
        r.x = fmaxf(acc[im][0] + be[0], 0.f) * w;
        r.y = fmaxf(acc[im][1] + be[1], 0.f) * w;
        r.z = fmaxf(acc[im][2] + be[2], 0.f) * w;
        r.w = fmaxf(acc[im][3] + be[3], 0.f) * w;
        *(float4*)(g_F + (size_t)pair * KD + n0 + tx * 4) = r;
    }
}

// ---------------- decode: per-token top-50 select + gather-accumulate ----------------
__global__ void __launch_bounds__(256) k_decode(const float* __restrict__ b_dec,
                                                const float* __restrict__ Wdec,
                                                float* __restrict__ out) {
    int b = blockIdx.x;
    int tid = threadIdx.x;

    __shared__ float sf[KD];
    __shared__ int   sel[64];
    __shared__ int   s_nsel;
    __shared__ int   s_red[8];

    float acc0 = b_dec[tid];
    float acc1 = b_dec[tid + 256];
    float acc2 = b_dec[tid + 512];

    for (int slot = 0; slot < 2; slot++) {
        int pair = b * 2 + slot;
        int e = g_route[pair];
        const float* Fr = g_F + (size_t)pair * KD;

        unsigned rv[6];
#pragma unroll
        for (int j = 0; j < 6; j++) {
            float v = Fr[tid + 256 * j];
            sf[tid + 256 * j] = v;
            rv[j] = __float_as_uint(v);
        }
        __syncthreads();

        // binary search: largest t with count(bits >= t) >= KSEL
        // f >= 0 so uint compare is value-monotone. Invariant: c(lo)>=K, c(hi)<K.
        unsigned lo = 0u, hi = 0x7f800000u;
        while (hi - lo > 1u) {
            unsigned mid = lo + ((hi - lo) >> 1);
            int c = 0;
#pragma unroll
            for (int j = 0; j < 6; j++) c += (rv[j] >= mid);
            c = __reduce_add_sync(0xffffffffu, c);
            if ((tid & 31) == 0) s_red[tid >> 5] = c;
            __syncthreads();
            int tot = 0;
#pragma unroll
            for (int wrp = 0; wrp < 8; wrp++) tot += s_red[wrp];
            __syncthreads();
            if (tot >= KSEL) lo = mid; else hi = mid;
        }
        unsigned thr = lo;

        // order-preserving compaction by warp 0 (exclude exact zeros, cap KSEL)
        if (tid < 32) {
            int ns = 0;
            for (int base = 0; base < KD; base += 32) {
                unsigned bits = __float_as_uint(sf[base + tid]);
                bool p = (bits >= thr) && (bits != 0u);
                unsigned msk = __ballot_sync(0xffffffffu, p);
                int pos = ns + __popc(msk & ((1u << tid) - 1u));
                if (p && pos < KSEL) sel[pos] = base + tid;
                ns += __popc(msk);
            }
            if (tid == 0) s_nsel = (ns < KSEL ? ns : KSEL);
        }
        __syncthreads();
        int nsel = s_nsel;

        const float* Wd = Wdec + (size_t)e * KD * DIM;
        for (int i = 0; i < nsel; i++) {
            int k = sel[i];
            float fv = sf[k];
            const float* wr = Wd + (size_t)k * DIM;
            acc0 += fv * wr[tid];
            acc1 += fv * wr[tid + 256];
            acc2 += fv * wr[tid + 512];
        }
        __syncthreads();   // before sf is overwritten for next slot
    }

    out[(size_t)b * DIM + tid]       = acc0;
    out[(size_t)b * DIM + tid + 256] = acc1;
    out[(size_t)b * DIM + tid + 512] = acc2;
}

// ---------------- launch ----------------
extern "C" void kernel_launch(void* const* d_in, const int* in_sizes, int n_in,
                              void* d_out, int out_size) {
    const float* x      = (const float*)d_in[0];
    const float* Wg     = (const float*)d_in[1];
    const float* bg     = (const float*)d_in[2];
    const float* b_gate = (const float*)d_in[3];
    const float* b_dec  = (const float*)d_in[4];
    const float* Wenc   = (const float*)d_in[5];
    const float* benc   = (const float*)d_in[6];
    const float* Wdec   = (const float*)d_in[7];
    float* out = (float*)d_out;

    k_init<<<1, 32>>>();
    k_gate<<<BATCH / 4, 128>>>(x, Wg, bg, b_gate);
    k_encode<<<dim3(KD / TN, NEXP * 64), 256>>>(x, b_dec, Wenc, benc);
    k_decode<<<BATCH, 256>>>(b_dec, Wdec, out);
}

// round 4
// speedup vs baseline: 1.2129x; 1.2129x over previous
#include <cuda_runtime.h>
#include <cstdint>

#define BATCH 4096
#define DIM   768
#define NEXP  16
#define KD    1536
#define KSEL  50
#define NPAIR (BATCH*2)

// ---------------- f32x2 packed-math macros ----------------
#define FMA2(d,a,b) asm("fma.rn.f32x2 %0, %1, %2, %3;" : "=l"(d) : "l"(a), "l"(b), "l"(d))
#define PACK2(d,lo,hi) asm("mov.b64 %0, {%1, %2};" : "=l"(d) : "f"(lo), "f"(hi))
#define UNPACK2(lo,hi,v) asm("mov.b64 {%0, %1}, %2;" : "=f"(lo), "=f"(hi) : "l"(v))
typedef unsigned long long u64;

// ---------------- device scratch ----------------
__device__ float g_F[NPAIR * KD];       // masked relu activations, 50.3 MB
__device__ float g_w[NPAIR];            // gate weight per (token,slot)
__device__ int   g_route[NPAIR];        // expert id per (token,slot)
__device__ int   g_cnt[NEXP];
__device__ int   g_list[NEXP * BATCH];

// ---------------- init ----------------
__global__ void k_init() {
    if (threadIdx.x < NEXP) g_cnt[threadIdx.x] = 0;
}

// ---------------- gate + route: one warp per token ----------------
__global__ void __launch_bounds__(128) k_gate(const float* __restrict__ x,
                                              const float* __restrict__ Wg,
                                              const float* __restrict__ bg,
                                              const float* __restrict__ b_gate) {
    int b = blockIdx.x * 4 + (threadIdx.x >> 5);
    int lane = threadIdx.x & 31;
    const float* xr = x + (size_t)b * DIM;

    float pe[NEXP];
#pragma unroll
    for (int e = 0; e < NEXP; e++) pe[e] = 0.f;
    for (int d = lane; d < DIM; d += 32) {
        float xv = xr[d] - b_gate[d];
#pragma unroll
        for (int e = 0; e < NEXP; e++) pe[e] += xv * Wg[e * DIM + d];
    }
#pragma unroll
    for (int e = 0; e < NEXP; e++) {
#pragma unroll
        for (int o = 16; o > 0; o >>= 1) pe[e] += __shfl_xor_sync(0xffffffffu, pe[e], o);
        pe[e] += bg[e];
    }
    float m = pe[0];
#pragma unroll
    for (int e = 1; e < NEXP; e++) m = fmaxf(m, pe[e]);
    float s = 0.f;
#pragma unroll
    for (int e = 0; e < NEXP; e++) { pe[e] = expf(pe[e] - m); s += pe[e]; }
    float inv = 1.f / s;
    float v1 = -1.f, v2 = -1.f; int i1 = 0, i2 = 0;
#pragma unroll
    for (int e = 0; e < NEXP; e++) {
        float p = pe[e] * inv;
        if (p > v1)      { v2 = v1; i2 = i1; v1 = p; i1 = e; }
        else if (p > v2) { v2 = p;  i2 = e; }
    }
    float e1 = expf(v1), e2 = expf(v2);
    float w0 = e1 / (e1 + e2), w1 = e2 / (e1 + e2);

    if (lane == 0) {
        int p0 = b * 2, p1 = b * 2 + 1;
        g_route[p0] = i1; g_route[p1] = i2;
        g_w[p0] = w0;     g_w[p1] = w1;
        int q0 = atomicAdd(&g_cnt[i1], 1); g_list[i1 * BATCH + q0] = p0;
        int q1 = atomicAdd(&g_cnt[i2], 1); g_list[i2 * BATCH + q1] = p1;
    }
}

// ---------------- grouped encode GEMM (f32x2 packed) ----------------
// tile 128(M pairs) x 128(N dict), K-chunks of 8, 256 threads, 8x8 microtile
#define TM 128
#define TN 128
#define TK 8
#define LDP 132   // padded row stride (floats), 16B multiple

struct __align__(16) SmemEnc {
    float Xs[2][TK][LDP];
    float Ws[2][TK][LDP];
    int   pair[TM];
};

__global__ void __launch_bounds__(256, 2) k_encode(const float* __restrict__ x,
                                                   const float* __restrict__ b_dec,
                                                   const float* __restrict__ Wenc,
                                                   const float* __restrict__ benc) {
    __shared__ SmemEnc sm;
    int e  = blockIdx.y >> 5;
    int mt = blockIdx.y & 31;
    int cnt = g_cnt[e];
    int m0 = mt * TM;
    if (m0 >= cnt) return;
    int n0 = blockIdx.x * TN;

    int tid = threadIdx.x;
    if (tid < TM) {
        int m = m0 + tid;
        sm.pair[tid] = (m < cnt) ? g_list[e * BATCH + m] : -1;
    }
    __syncthreads();

    int tx = tid & 15, ty = tid >> 4;

    u64 acc[8][4];
#pragma unroll
    for (int i = 0; i < 8; i++)
#pragma unroll
        for (int j = 0; j < 4; j++) acc[i][j] = 0ULL;

    // loader mapping: thread -> one float4 of X and one of W per chunk
    int lr = tid >> 1;            // 0..127
    int kc = (tid & 1) * 4;       // 0 or 4
    int pairL = sm.pair[lr];
    int tokenL = (pairL >= 0 ? pairL : 0) >> 1;
    const float* xrow = x + (size_t)tokenL * DIM + kc;
    const float* wrow = Wenc + (size_t)e * KD * DIM + (size_t)(n0 + lr) * DIM + kc;
    const float* brow = b_dec + kc;

    float4 nx = *(const float4*)(xrow);
    float4 nb = *(const float4*)(brow);
    float4 nw = *(const float4*)(wrow);
    nx.x -= nb.x; nx.y -= nb.y; nx.z -= nb.z; nx.w -= nb.w;
    sm.Xs[0][kc + 0][lr] = nx.x; sm.Xs[0][kc + 1][lr] = nx.y;
    sm.Xs[0][kc + 2][lr] = nx.z; sm.Xs[0][kc + 3][lr] = nx.w;
    sm.Ws[0][kc + 0][lr] = nw.x; sm.Ws[0][kc + 1][lr] = nw.y;
    sm.Ws[0][kc + 2][lr] = nw.z; sm.Ws[0][kc + 3][lr] = nw.w;
    __syncthreads();

    int buf = 0;
#pragma unroll 1
    for (int c = 1; c < DIM / TK; c++) {
        nx = *(const float4*)(xrow + c * TK);
        nb = *(const float4*)(brow + c * TK);
        nw = *(const float4*)(wrow + c * TK);
        nx.x -= nb.x; nx.y -= nb.y; nx.z -= nb.z; nx.w -= nb.w;
#pragma unroll
        for (int kk = 0; kk < TK; kk++) {
            float4 a0 = *(const float4*)&sm.Xs[buf][kk][ty * 8];
            float4 a1 = *(const float4*)&sm.Xs[buf][kk][ty * 8 + 4];
            ulonglong2 b0 = *(const ulonglong2*)&sm.Ws[buf][kk][tx * 8];
            ulonglong2 b1 = *(const ulonglong2*)&sm.Ws[buf][kk][tx * 8 + 4];
            float av[8] = {a0.x, a0.y, a0.z, a0.w, a1.x, a1.y, a1.z, a1.w};
#pragma unroll
            for (int i = 0; i < 8; i++) {
                u64 ad; PACK2(ad, av[i], av[i]);
                FMA2(acc[i][0], ad, b0.x);
                FMA2(acc[i][1], ad, b0.y);
                FMA2(acc[i][2], ad, b1.x);
                FMA2(acc[i][3], ad, b1.y);
            }
        }
        int nbuf = buf ^ 1;
        sm.Xs[nbuf][kc + 0][lr] = nx.x; sm.Xs[nbuf][kc + 1][lr] = nx.y;
        sm.Xs[nbuf][kc + 2][lr] = nx.z; sm.Xs[nbuf][kc + 3][lr] = nx.w;
        sm.Ws[nbuf][kc + 0][lr] = nw.x; sm.Ws[nbuf][kc + 1][lr] = nw.y;
        sm.Ws[nbuf][kc + 2][lr] = nw.z; sm.Ws[nbuf][kc + 3][lr] = nw.w;
        __syncthreads();
        buf = nbuf;
    }
    // last chunk
#pragma unroll
    for (int kk = 0; kk < TK; kk++) {
        float4 a0 = *(const float4*)&sm.Xs[buf][kk][ty * 8];
        float4 a1 = *(const float4*)&sm.Xs[buf][kk][ty * 8 + 4];
        ulonglong2 b0 = *(const ulonglong2*)&sm.Ws[buf][kk][tx * 8];
        ulonglong2 b1 = *(const ulonglong2*)&sm.Ws[buf][kk][tx * 8 + 4];
        float av[8] = {a0.x, a0.y, a0.z, a0.w, a1.x, a1.y, a1.z, a1.w};
#pragma unroll
        for (int i = 0; i < 8; i++) {
            u64 ad; PACK2(ad, av[i], av[i]);
            FMA2(acc[i][0], ad, b0.x);
            FMA2(acc[i][1], ad, b0.y);
            FMA2(acc[i][2], ad, b1.x);
            FMA2(acc[i][3], ad, b1.y);
        }
    }

    // epilogue: bias + relu + gate-weight, store to g_F
    const float* be = benc + (size_t)e * KD + n0 + tx * 8;
    float4 bl = *(const float4*)(be);
    float4 bh = *(const float4*)(be + 4);
#pragma unroll
    for (int i = 0; i < 8; i++) {
        int m = ty * 8 + i;
        int pair = sm.pair[m];
        if (pair < 0) continue;
        float w = g_w[pair];
        float c0, c1, c2, c3, c4, c5, c6, c7;
        UNPACK2(c0, c1, acc[i][0]);
        UNPACK2(c2, c3, acc[i][1]);
        UNPACK2(c4, c5, acc[i][2]);
        UNPACK2(c6, c7, acc[i][3]);
        float4 r0, r1;
        r0.x = fmaxf(c0 + bl.x, 0.f) * w; r0.y = fmaxf(c1 + bl.y, 0.f) * w;
        r0.z = fmaxf(c2 + bl.z, 0.f) * w; r0.w = fmaxf(c3 + bl.w, 0.f) * w;
        r1.x = fmaxf(c4 + bh.x, 0.f) * w; r1.y = fmaxf(c5 + bh.y, 0.f) * w;
        r1.z = fmaxf(c6 + bh.z, 0.f) * w; r1.w = fmaxf(c7 + bh.w, 0.f) * w;
        float* dst = g_F + (size_t)pair * KD + n0 + tx * 8;
        *(float4*)(dst)     = r0;
        *(float4*)(dst + 4) = r1;
    }
}

// ---------------- decode: top-50 select + vectorized gather ----------------
__global__ void __launch_bounds__(192) k_decode(const float* __restrict__ b_dec,
                                                const float* __restrict__ Wdec,
                                                float* __restrict__ out) {
    int b = blockIdx.x;
    int tid = threadIdx.x;

    __shared__ float sf[KD];
    __shared__ int   sel[64];
    __shared__ int   s_nsel;
    __shared__ int   s_red[6];

    float4 bd = *(const float4*)(b_dec + tid * 4);
    u64 acc01, acc23;
    PACK2(acc01, bd.x, bd.y);
    PACK2(acc23, bd.z, bd.w);

    for (int slot = 0; slot < 2; slot++) {
        int pair = b * 2 + slot;
        int e = g_route[pair];
        const float* Fr = g_F + (size_t)pair * KD;

        unsigned rv[8];
#pragma unroll
        for (int j = 0; j < 8; j++) {
            float v = Fr[tid + 192 * j];
            sf[tid + 192 * j] = v;
            rv[j] = __float_as_uint(v);
        }
        __syncthreads();

        // binary search: largest t with count(bits >= t) >= KSEL (f >= 0 -> uint monotone)
        unsigned lo = 0u, hi = 0x7f800000u;
        while (hi - lo > 1u) {
            unsigned mid = lo + ((hi - lo) >> 1);
            int c = 0;
#pragma unroll
            for (int j = 0; j < 8; j++) c += (rv[j] >= mid);
            c = __reduce_add_sync(0xffffffffu, c);
            if ((tid & 31) == 0) s_red[tid >> 5] = c;
            __syncthreads();
            int tot = 0;
#pragma unroll
            for (int wrp = 0; wrp < 6; wrp++) tot += s_red[wrp];
            __syncthreads();
            if (tot >= KSEL) lo = mid; else hi = mid;
        }
        unsigned thr = lo;

        // order-preserving compaction by warp 0 (exclude exact zeros, cap KSEL)
        if (tid < 32) {
            int ns = 0;
            for (int base = 0; base < KD; base += 32) {
                unsigned bits = __float_as_uint(sf[base + tid]);
                bool p = (bits >= thr) && (bits != 0u);
                unsigned msk = __ballot_sync(0xffffffffu, p);
                int pos = ns + __popc(msk & ((1u << tid) - 1u));
                if (p && pos < KSEL) sel[pos] = base + tid;
                ns += __popc(msk);
            }
            if (tid == 0) s_nsel = (ns < KSEL ? ns : KSEL);
        }
        __syncthreads();
        int nsel = s_nsel;

        const float* Wd = Wdec + (size_t)e * KD * DIM + tid * 4;
        int i = 0;
        for (; i + 2 <= nsel; i += 2) {
            int k0 = sel[i], k1 = sel[i + 1];
            float f0 = sf[k0], f1 = sf[k1];
            float4 w0 = *(const float4*)(Wd + (size_t)k0 * DIM);
            float4 w1 = *(const float4*)(Wd + (size_t)k1 * DIM);
            u64 fp0, fp1, t;
            PACK2(fp0, f0, f0);
            PACK2(fp1, f1, f1);
            PACK2(t, w0.x, w0.y); FMA2(acc01, fp0, t);
            PACK2(t, w0.z, w0.w); FMA2(acc23, fp0, t);
            PACK2(t, w1.x, w1.y); FMA2(acc01, fp1, t);
            PACK2(t, w1.z, w1.w); FMA2(acc23, fp1, t);
        }
        for (; i < nsel; i++) {
            int k0 = sel[i];
            float f0 = sf[k0];
            float4 w0 = *(const float4*)(Wd + (size_t)k0 * DIM);
            u64 fp0, t;
            PACK2(fp0, f0, f0);
            PACK2(t, w0.x, w0.y); FMA2(acc01, fp0, t);
            PACK2(t, w0.z, w0.w); FMA2(acc23, fp0, t);
        }
        __syncthreads();   // before sf is overwritten for next slot
    }

    float4 r;
    UNPACK2(r.x, r.y, acc01);
    UNPACK2(r.z, r.w, acc23);
    *(float4*)(out + (size_t)b * DIM + tid * 4) = r;
}

// ---------------- launch ----------------
extern "C" void kernel_launch(void* const* d_in, const int* in_sizes, int n_in,
                              void* d_out, int out_size) {
    const float* x      = (const float*)d_in[0];
    const float* Wg     = (const float*)d_in[1];
    const float* bg     = (const float*)d_in[2];
    const float* b_gate = (const float*)d_in[3];
    const float* b_dec  = (const float*)d_in[4];
    const float* Wenc   = (const float*)d_in[5];
    const float* benc   = (const float*)d_in[6];
    const float* Wdec   = (const float*)d_in[7];
    float* out = (float*)d_out;

    k_init<<<1, 32>>>();
    k_gate<<<BATCH / 4, 128>>>(x, Wg, bg, b_gate);
    k_encode<<<dim3(KD / TN, NEXP * 32), 256>>>(x, b_dec, Wenc, benc);
    k_decode<<<BATCH, 192>>>(b_dec, Wdec, out);
}